// round 17
// baseline (speedup 1.0000x reference)
#include <cuda_runtime.h>
#include <cuda_bf16.h>
#include <math.h>
#include <stdint.h>

// Problem constants (fixed by reference)
#define NNODES 20000
#define NEDGES 320000
#define ETOT   340000   // NEDGES + NNODES self loops
#define INDIM  512
#define NHEAD  4
#define CDIM   64
#define HCDIM  256
#define NOUT   512      // dual-GEMM output width (xl | xr)
#define EPS_BN 1e-5f
#define SCAN_BLOCKS 20  // 20 * 1024 >= NNODES

// ---------------- scratch (device globals; no allocation allowed) ----------
__device__ float g_xlr[NNODES * NOUT];   // cols 0-255: xl, 256-511: xr
__device__ float g_h[NNODES * HCDIM];
__device__ float g_xl2[NNODES * 2];
__device__ float g_xr2[NNODES * 2];

// CSR by destination (src only)
__device__ int g_deg[NNODES];
__device__ int g_cursor[NNODES];
__device__ int g_rowptr[NNODES + 1];
__device__ int g_csr[ETOT];
__device__ int g_bsum[SCAN_BLOCKS];
__device__ int g_bflag[SCAN_BLOCKS];

// bf16 hi/lo split buffers for tensor-core GEMMs
__device__ __nv_bfloat16 g_xhi[NNODES * INDIM];
__device__ __nv_bfloat16 g_xlo[NNODES * INDIM];
__device__ __nv_bfloat16 g_hhi[NNODES * HCDIM];
__device__ __nv_bfloat16 g_hlo[NNODES * HCDIM];
// concatenated, transposed (N-major, K-contiguous) weight splits: [512, K]
__device__ __nv_bfloat16 g_w0h[NOUT * INDIM];
__device__ __nv_bfloat16 g_w0l[NOUT * INDIM];
__device__ __nv_bfloat16 g_w1h[NOUT * HCDIM];
__device__ __nv_bfloat16 g_w1l[NOUT * HCDIM];

// ---------------- PTX helpers ----------------------------------------------
__device__ __forceinline__ uint32_t smem_to_u32(const void* smem_ptr) {
    uint32_t addr;
    asm("{ .reg .u64 tmp; cvta.to.shared.u64 tmp, %1; cvt.u32.u64 %0, tmp; }"
        : "=r"(addr) : "l"(smem_ptr));
    return addr;
}

__device__ __forceinline__ void cp_async16(uint32_t dst, const void* src) {
    asm volatile("cp.async.cg.shared.global [%0], [%1], 16;" :: "r"(dst), "l"(src));
}
#define CP_COMMIT() asm volatile("cp.async.commit_group;" ::: "memory")
#define CP_WAIT(n)  asm volatile("cp.async.wait_group %0;" :: "n"(n) : "memory")

__device__ __forceinline__ void ldsm_x4(uint32_t (&r)[4], uint32_t addr) {
    asm volatile("ldmatrix.sync.aligned.m8n8.x4.shared.b16 {%0,%1,%2,%3}, [%4];"
                 : "=r"(r[0]), "=r"(r[1]), "=r"(r[2]), "=r"(r[3]) : "r"(addr));
}
__device__ __forceinline__ void ldsm_x2(uint32_t (&r)[2], uint32_t addr) {
    asm volatile("ldmatrix.sync.aligned.m8n8.x2.shared.b16 {%0,%1}, [%2];"
                 : "=r"(r[0]), "=r"(r[1]) : "r"(addr));
}
__device__ __forceinline__ void mma_bf16(float (&d)[4], const uint32_t (&a)[4],
                                         const uint32_t (&b)[2]) {
    asm volatile("mma.sync.aligned.m16n8k16.row.col.f32.bf16.bf16.f32 "
                 "{%0,%1,%2,%3}, {%4,%5,%6,%7}, {%8,%9}, {%0,%1,%2,%3};"
                 : "+f"(d[0]), "+f"(d[1]), "+f"(d[2]), "+f"(d[3])
                 : "r"(a[0]), "r"(a[1]), "r"(a[2]), "r"(a[3]),
                   "r"(b[0]), "r"(b[1]));
}

__device__ __forceinline__ void red_add_v2(float* ptr, float x, float y) {
    asm volatile("red.global.add.v2.f32 [%0], {%1, %2};"
                 :: "l"(ptr), "f"(x), "f"(y) : "memory");
}

__device__ __forceinline__ void edge_endpoints(const int* __restrict__ ei, int e,
                                               int& src, int& dst) {
    if (e < NEDGES) { src = ei[e]; dst = ei[NEDGES + e]; }
    else            { src = e - NEDGES; dst = src; }
}

// ---------------- CSR build -------------------------------------------------
__global__ void deg_kernel(const int* __restrict__ ei, int* __restrict__ deg) {
    int t = blockIdx.x * blockDim.x + threadIdx.x;
    if (t >= ETOT) return;
    int dst = (t < NEDGES) ? ei[NEDGES + t] : t - NEDGES;
    atomicAdd(&deg[dst], 1);
}

// multi-block chained exclusive scan: 20 blocks x 1024, 1 element/thread.
// Chained prefix via volatile bsum/bflag (flags pre-zeroed in xsplit).
__global__ void scan_kernel(const int* __restrict__ deg,
                            int* __restrict__ rowptr,
                            int* __restrict__ cursor,
                            volatile int* bsum,
                            volatile int* bflag) {
    int tid = threadIdx.x;
    int blk = blockIdx.x;
    int gid = blk * 1024 + tid;
    int v = (gid < NNODES) ? deg[gid] : 0;

    // block exclusive scan (warp shfl + warp-sums scan)
    int lane = tid & 31, wid = tid >> 5;
    int inc = v;
#pragma unroll
    for (int off = 1; off < 32; off <<= 1) {
        int n = __shfl_up_sync(0xFFFFFFFFu, inc, off);
        if (lane >= off) inc += n;
    }
    __shared__ int wsum[32];
    if (lane == 31) wsum[wid] = inc;
    __syncthreads();
    if (tid < 32) {
        int wv = wsum[tid];
#pragma unroll
        for (int off = 1; off < 32; off <<= 1) {
            int n = __shfl_up_sync(0xFFFFFFFFu, wv, off);
            if (tid >= off) wv += n;
        }
        wsum[tid] = wv;
    }
    __syncthreads();
    int excl = ((wid == 0) ? 0 : wsum[wid - 1]) + inc - v;
    int total = wsum[31];

    // chained prefix
    __shared__ int sprefix;
    if (tid == 0) {
        int prefix = 0;
        if (blk > 0) {
            while (bflag[blk - 1] == 0) { }
            prefix = bsum[blk - 1];
        }
        bsum[blk] = prefix + total;
        __threadfence();
        bflag[blk] = 1;
        sprefix = prefix;
    }
    __syncthreads();
    int e = excl + sprefix;
    if (gid < NNODES) { rowptr[gid] = e; cursor[gid] = e; }
    if (blk == SCAN_BLOCKS - 1 && tid == 0) rowptr[NNODES] = sprefix + total;
}

__global__ void scatter_kernel(const int* __restrict__ ei,
                               int* __restrict__ cursor,
                               int* __restrict__ csr) {
    int t = blockIdx.x * blockDim.x + threadIdx.x;
    if (t >= ETOT) return;
    int src, dst;
    edge_endpoints(ei, t, src, dst);
    int pos = atomicAdd(&cursor[dst], 1);
    csr[pos] = src;
}

// ---------------- bf16 split kernels ---------------------------------------
// also zeroes deg histogram, scan flags, and xl2/xr2 accumulators
__global__ void xsplit_kernel(const float* __restrict__ X, int n,
                              __nv_bfloat16* __restrict__ Xh,
                              __nv_bfloat16* __restrict__ Xl,
                              int* __restrict__ deg,
                              float* __restrict__ xl2,
                              float* __restrict__ xr2,
                              int* __restrict__ bflag) {
    int i = blockIdx.x * blockDim.x + threadIdx.x;
    if (i < NNODES) deg[i] = 0;
    if (i < NNODES * 2) { xl2[i] = 0.f; xr2[i] = 0.f; }
    if (i < SCAN_BLOCKS) bflag[i] = 0;
    if (i >= n) return;
    float v = X[i];
    __nv_bfloat16 h = __float2bfloat16(v);
    Xh[i] = h;
    Xl[i] = __float2bfloat16(v - __bfloat162float(h));
}

// All 4 weight transposes in one launch (blockIdx.z selects matrix).
__global__ void wtrans_all_kernel(const float* __restrict__ Wl0,
                                  const float* __restrict__ Wr0,
                                  const float* __restrict__ Wl1,
                                  const float* __restrict__ Wr1,
                                  __nv_bfloat16* __restrict__ w0h,
                                  __nv_bfloat16* __restrict__ w0l,
                                  __nv_bfloat16* __restrict__ w1h,
                                  __nv_bfloat16* __restrict__ w1l) {
    int z = blockIdx.z;
    const float* W;
    __nv_bfloat16 *Wh, *Wl;
    int K;
    if (z == 0)      { W = Wl0; K = INDIM; Wh = w0h;               Wl = w0l; }
    else if (z == 1) { W = Wr0; K = INDIM; Wh = w0h + 256 * INDIM; Wl = w0l + 256 * INDIM; }
    else if (z == 2) { W = Wl1; K = HCDIM; Wh = w1h;               Wl = w1l; }
    else             { W = Wr1; K = HCDIM; Wh = w1h + 256 * HCDIM; Wl = w1l + 256 * HCDIM; }
    int k0 = blockIdx.x * 32;
    if (k0 >= K) return;
    int n0 = blockIdx.y * 32;
    __shared__ float tile[32][33];
    int tx = threadIdx.x, ty = threadIdx.y;   // (32, 8)
#pragma unroll
    for (int i = 0; i < 4; i++) {
        int k = k0 + ty + i * 8;
        tile[ty + i * 8][tx] = W[(size_t)k * HCDIM + n0 + tx];
    }
    __syncthreads();
#pragma unroll
    for (int i = 0; i < 4; i++) {
        int n = n0 + ty + i * 8;
        float v = tile[tx][ty + i * 8];
        __nv_bfloat16 h = __float2bfloat16(v);
        Wh[(size_t)n * K + k0 + tx] = h;
        Wl[(size_t)n * K + k0 + tx] = __float2bfloat16(v - __bfloat162float(h));
    }
}

// ---------------- HMMA dual GEMM (3-stage pipeline, 2 CTAs/SM, K templated) -
#define GSTAGE 32768
#define GSMEM  (3 * GSTAGE)

template <int K>
__global__ void __launch_bounds__(256, 2)
hmma_dual_gemm(const __nv_bfloat16* __restrict__ Ah,
               const __nv_bfloat16* __restrict__ Al,
               const __nv_bfloat16* __restrict__ Bh,
               const __nv_bfloat16* __restrict__ Bl,
               float* __restrict__ C, int M) {
    extern __shared__ char smem[];
    uint32_t sb = smem_to_u32(smem);
    int tid = threadIdx.x;
    int lane = tid & 31, wid = tid >> 5;
    int wm = wid >> 2, wn = wid & 3;
    int mBase = blockIdx.y * 128;
    int nBase = blockIdx.x * 128;
    constexpr int nq = K >> 5;

    float acc[4][4][4];
#pragma unroll
    for (int a = 0; a < 4; a++)
#pragma unroll
        for (int b = 0; b < 4; b++)
#pragma unroll
            for (int c = 0; c < 4; c++) acc[a][b][c] = 0.f;

    auto load_stage = [&](int q, int s) {
        int k0 = q << 5;
        uint32_t base = sb + s * GSTAGE;
        char* sm = smem + s * GSTAGE;
#pragma unroll
        for (int it = 0; it < 2; it++) {
            int idx = tid + it * 256;
            int r = idx >> 2, c = idx & 3;
            uint32_t dsw = r * 64 + ((c ^ (r & 3)) << 4);
            int R = mBase + r;
            if (R < M) {
                const char* sh = (const char*)(Ah + (size_t)R * K + k0) + c * 16;
                const char* sl = (const char*)(Al + (size_t)R * K + k0) + c * 16;
                cp_async16(base + dsw, sh);
                cp_async16(base + 8192 + dsw, sl);
            } else {
                uint4 z = make_uint4(0, 0, 0, 0);
                *(uint4*)(sm + dsw) = z;
                *(uint4*)(sm + 8192 + dsw) = z;
            }
        }
#pragma unroll
        for (int it = 0; it < 2; it++) {
            int idx = tid + it * 256;
            int r = idx >> 2, c = idx & 3;
            uint32_t dsw = r * 64 + ((c ^ (r & 3)) << 4);
            int NR = nBase + r;
            const char* sh = (const char*)(Bh + (size_t)NR * K + k0) + c * 16;
            const char* sl = (const char*)(Bl + (size_t)NR * K + k0) + c * 16;
            cp_async16(base + 16384 + dsw, sh);
            cp_async16(base + 24576 + dsw, sl);
        }
    };

    load_stage(0, 0); CP_COMMIT();
    load_stage(1, 1); CP_COMMIT();

    int stage = 0;
    for (int q = 0; q < nq; q++) {
        if (q + 2 < nq) {
            int s2 = stage + 2; if (s2 >= 3) s2 -= 3;
            load_stage(q + 2, s2); CP_COMMIT();
            CP_WAIT(2);
        } else if (q + 1 < nq) {
            CP_WAIT(1);
        } else {
            CP_WAIT(0);
        }
        __syncthreads();
        uint32_t base = sb + stage * GSTAGE;

#pragma unroll
        for (int step = 0; step < 2; step++) {
            uint32_t ahf[4][4], alf[4][4], bhf[4][2], blf[4][2];
            int arow = wm * 64 + (lane & 15);
            int ac = 2 * step + (lane >> 4);
#pragma unroll
            for (int mi = 0; mi < 4; mi++) {
                int r = arow + mi * 16;
                uint32_t ad = base + r * 64 + ((ac ^ (r & 3)) << 4);
                ldsm_x4(ahf[mi], ad);
                ldsm_x4(alf[mi], ad + 8192);
            }
#pragma unroll
            for (int nj = 0; nj < 4; nj++) {
                int r = wn * 32 + nj * 8 + (lane & 7);
                int bc = 2 * step + ((lane >> 3) & 1);
                uint32_t bd = base + 16384 + r * 64 + ((bc ^ (r & 3)) << 4);
                ldsm_x2(bhf[nj], bd);
                ldsm_x2(blf[nj], bd + 8192);
            }
            // product-major ordering: 16 independent accumulators between revisits
#pragma unroll
            for (int mi = 0; mi < 4; mi++)
#pragma unroll
                for (int nj = 0; nj < 4; nj++)
                    mma_bf16(acc[mi][nj], ahf[mi], bhf[nj]);
#pragma unroll
            for (int mi = 0; mi < 4; mi++)
#pragma unroll
                for (int nj = 0; nj < 4; nj++)
                    mma_bf16(acc[mi][nj], ahf[mi], blf[nj]);
#pragma unroll
            for (int mi = 0; mi < 4; mi++)
#pragma unroll
                for (int nj = 0; nj < 4; nj++)
                    mma_bf16(acc[mi][nj], alf[mi], bhf[nj]);
        }
        __syncthreads();
        if (++stage == 3) stage = 0;
    }

    int rBase = mBase + wm * 64;
    int cBase = nBase + wn * 32;
#pragma unroll
    for (int mi = 0; mi < 4; mi++) {
        int r0 = rBase + mi * 16 + (lane >> 2);
#pragma unroll
        for (int nj = 0; nj < 4; nj++) {
            int cc = cBase + nj * 8 + 2 * (lane & 3);
            if (r0 < M)
                *(float2*)(C + (size_t)r0 * NOUT + cc) =
                    make_float2(acc[mi][nj][0], acc[mi][nj][1]);
            if (r0 + 8 < M)
                *(float2*)(C + (size_t)(r0 + 8) * NOUT + cc) =
                    make_float2(acc[mi][nj][2], acc[mi][nj][3]);
        }
    }
}

// ---------------- fused GATv2 layer (score + softmax-agg + BN + ELU) --------
// TWO warps per node (warp half = 2 heads = 128 channels); lane owns 4 channels.
// Optionally fuses the layer-2 projection (h @ Wl2 / Wr2, 256->2) into the
// epilogue via per-lane dot + warp reduce + one red.add.v2 per warp.
__global__ void node_gat_kernel(const int* __restrict__ rowptr,
                                const int* __restrict__ csr,
                                const float* __restrict__ xlr,
                                const float* __restrict__ att,
                                const float* __restrict__ b,
                                const float* __restrict__ g,
                                const float* __restrict__ be,
                                const float* __restrict__ m,
                                const float* __restrict__ v,
                                float* __restrict__ hout,
                                __nv_bfloat16* __restrict__ outh,
                                __nv_bfloat16* __restrict__ outl,
                                const float* __restrict__ Wl2,
                                const float* __restrict__ Wr2,
                                float* __restrict__ xl2,
                                float* __restrict__ xr2,
                                int doProj) {
    int gw = (blockIdx.x * blockDim.x + threadIdx.x) >> 5;
    int w = gw >> 1;
    if (w >= NNODES) return;
    int half = gw & 1;
    int lane = threadIdx.x & 31;
    int col = half * 128 + lane * 4;
    int p0 = rowptr[w], p1 = rowptr[w + 1];

    float4 r4 = *(const float4*)(xlr + (size_t)w * NOUT + 256 + col);
    float4 a4 = *(const float4*)(att + col);
    float4 acc = make_float4(0.f, 0.f, 0.f, 0.f);
    float dsum = 0.f;

    for (int base = p0; base < p1; base += 32) {
        int se = 0;
        if (base + lane < p1) se = csr[base + lane];
        int cnt = min(32, p1 - base);
        int j = 0;
        for (; j + 2 <= cnt; j += 2) {
            int s0 = __shfl_sync(0xFFFFFFFFu, se, j);
            int s1 = __shfl_sync(0xFFFFFFFFu, se, j + 1);
            float4 v0 = *(const float4*)(xlr + (size_t)s0 * NOUT + col);
            float4 v1 = *(const float4*)(xlr + (size_t)s1 * NOUT + col);
            float sc0, sc1, mv;
            mv = v0.x + r4.x; mv = mv > 0.f ? mv : 0.2f * mv; sc0  = mv * a4.x;
            mv = v0.y + r4.y; mv = mv > 0.f ? mv : 0.2f * mv; sc0 += mv * a4.y;
            mv = v0.z + r4.z; mv = mv > 0.f ? mv : 0.2f * mv; sc0 += mv * a4.z;
            mv = v0.w + r4.w; mv = mv > 0.f ? mv : 0.2f * mv; sc0 += mv * a4.w;
            mv = v1.x + r4.x; mv = mv > 0.f ? mv : 0.2f * mv; sc1  = mv * a4.x;
            mv = v1.y + r4.y; mv = mv > 0.f ? mv : 0.2f * mv; sc1 += mv * a4.y;
            mv = v1.z + r4.z; mv = mv > 0.f ? mv : 0.2f * mv; sc1 += mv * a4.z;
            mv = v1.w + r4.w; mv = mv > 0.f ? mv : 0.2f * mv; sc1 += mv * a4.w;
#pragma unroll
            for (int off = 1; off < 16; off <<= 1) {
                sc0 += __shfl_xor_sync(0xFFFFFFFFu, sc0, off);
                sc1 += __shfl_xor_sync(0xFFFFFFFFu, sc1, off);
            }
            float e0 = __expf(sc0), e1 = __expf(sc1);
            acc.x += e0 * v0.x + e1 * v1.x;
            acc.y += e0 * v0.y + e1 * v1.y;
            acc.z += e0 * v0.z + e1 * v1.z;
            acc.w += e0 * v0.w + e1 * v1.w;
            dsum += e0 + e1;
        }
        if (j < cnt) {
            int s0 = __shfl_sync(0xFFFFFFFFu, se, j);
            float4 v0 = *(const float4*)(xlr + (size_t)s0 * NOUT + col);
            float sc0, mv;
            mv = v0.x + r4.x; mv = mv > 0.f ? mv : 0.2f * mv; sc0  = mv * a4.x;
            mv = v0.y + r4.y; mv = mv > 0.f ? mv : 0.2f * mv; sc0 += mv * a4.y;
            mv = v0.z + r4.z; mv = mv > 0.f ? mv : 0.2f * mv; sc0 += mv * a4.z;
            mv = v0.w + r4.w; mv = mv > 0.f ? mv : 0.2f * mv; sc0 += mv * a4.w;
#pragma unroll
            for (int off = 1; off < 16; off <<= 1)
                sc0 += __shfl_xor_sync(0xFFFFFFFFu, sc0, off);
            float e0 = __expf(sc0);
            acc.x += e0 * v0.x; acc.y += e0 * v0.y;
            acc.z += e0 * v0.z; acc.w += e0 * v0.w;
            dsum += e0;
        }
    }
    float inv = 1.f / (dsum + 1e-16f);

    float4 b4 = *(const float4*)(b + col);
    float4 g4 = *(const float4*)(g + col);
    float4 e4 = *(const float4*)(be + col);
    float4 m4 = *(const float4*)(m + col);
    float4 v4 = *(const float4*)(v + col);

    float o[4];
    o[0] = acc.x * inv + b4.x; o[1] = acc.y * inv + b4.y;
    o[2] = acc.z * inv + b4.z; o[3] = acc.w * inv + b4.w;
    float gg[4] = {g4.x, g4.y, g4.z, g4.w};
    float ee[4] = {e4.x, e4.y, e4.z, e4.w};
    float mm[4] = {m4.x, m4.y, m4.z, m4.w};
    float vv[4] = {v4.x, v4.y, v4.z, v4.w};
#pragma unroll
    for (int i = 0; i < 4; i++) {
        float x = (o[i] - mm[i]) * (gg[i] * rsqrtf(vv[i] + EPS_BN)) + ee[i];
        x = x > 0.f ? x : (expf(x) - 1.0f);
        o[i] = x;
    }
    *(float4*)(hout + (size_t)w * HCDIM + col) = make_float4(o[0], o[1], o[2], o[3]);

    union { uint2 u; __nv_bfloat162 p[2]; } ph, pl;
#pragma unroll
    for (int i = 0; i < 2; i++) {
        __nv_bfloat16 h0 = __float2bfloat16(o[2 * i]);
        __nv_bfloat16 h1 = __float2bfloat16(o[2 * i + 1]);
        ph.p[i] = __nv_bfloat162(h0, h1);
        pl.p[i] = __nv_bfloat162(
            __float2bfloat16(o[2 * i] - __bfloat162float(h0)),
            __float2bfloat16(o[2 * i + 1] - __bfloat162float(h1)));
    }
    *(uint2*)(outh + (size_t)w * HCDIM + col) = ph.u;
    *(uint2*)(outl + (size_t)w * HCDIM + col) = pl.u;

    // fused layer-2 projection: partial dot over this lane's 4 channels
    if (doProj) {
        float l0 = 0.f, l1 = 0.f, q0 = 0.f, q1 = 0.f;
#pragma unroll
        for (int i = 0; i < 4; i++) {
            float2 wl = *(const float2*)(Wl2 + (col + i) * 2);
            float2 wr = *(const float2*)(Wr2 + (col + i) * 2);
            l0 += o[i] * wl.x; l1 += o[i] * wl.y;
            q0 += o[i] * wr.x; q1 += o[i] * wr.y;
        }
#pragma unroll
        for (int off = 16; off; off >>= 1) {
            l0 += __shfl_xor_sync(0xFFFFFFFFu, l0, off);
            l1 += __shfl_xor_sync(0xFFFFFFFFu, l1, off);
            q0 += __shfl_xor_sync(0xFFFFFFFFu, q0, off);
            q1 += __shfl_xor_sync(0xFFFFFFFFu, q1, off);
        }
        if (lane == 0) {
            red_add_v2(xl2 + w * 2, l0, l1);
            red_add_v2(xr2 + w * 2, q0, q1);
        }
    }
}

// Fused: scores + softmax-agg + bias + log_softmax. Warp per node, lane/edge.
__global__ void node_gat2_kernel(const int* __restrict__ rowptr,
                                 const int* __restrict__ csr,
                                 const float* __restrict__ xl2,
                                 const float* __restrict__ xr2,
                                 const float* __restrict__ att2,
                                 const float* __restrict__ b2,
                                 float* __restrict__ out) {
    int w = (blockIdx.x * blockDim.x + threadIdx.x) >> 5;
    int lane = threadIdx.x & 31;
    if (w >= NNODES) return;
    int p0 = rowptr[w], p1 = rowptr[w + 1];
    float2 r = *(const float2*)(xr2 + w * 2);
    float a0 = att2[0], a1 = att2[1];
    float s0 = 0.f, s1 = 0.f, ds = 0.f;
    for (int p = p0 + lane; p < p1; p += 32) {
        int src = csr[p];
        float2 l = *(const float2*)(xl2 + src * 2);
        float mx = l.x + r.x, my = l.y + r.y;
        mx = mx > 0.f ? mx : 0.2f * mx;
        my = my > 0.f ? my : 0.2f * my;
        float ex = __expf(mx * a0 + my * a1);
        s0 += ex * l.x; s1 += ex * l.y; ds += ex;
    }
#pragma unroll
    for (int off = 16; off; off >>= 1) {
        s0 += __shfl_xor_sync(0xFFFFFFFFu, s0, off);
        s1 += __shfl_xor_sync(0xFFFFFFFFu, s1, off);
        ds += __shfl_xor_sync(0xFFFFFFFFu, ds, off);
    }
    if (lane == 0) {
        float inv = 1.f / (ds + 1e-16f);
        float o0 = s0 * inv + b2[0];
        float o1 = s1 * inv + b2[1];
        float mx = fmaxf(o0, o1);
        float lse = mx + logf(expf(o0 - mx) + expf(o1 - mx));
        *(float2*)(out + w * 2) = make_float2(o0 - lse, o1 - lse);
    }
}

// ---------------- launch ---------------------------------------------------
extern "C" void kernel_launch(void* const* d_in, const int* in_sizes, int n_in,
                              void* d_out, int out_size) {
    const float* x   = (const float*)d_in[0];
    const int*   ei  = (const int*)d_in[1];
    const float* Wl0 = (const float*)d_in[2];
    const float* Wr0 = (const float*)d_in[3];
    const float* att0= (const float*)d_in[4];
    const float* b0  = (const float*)d_in[5];
    const float* g0  = (const float*)d_in[6];
    const float* be0 = (const float*)d_in[7];
    const float* m0  = (const float*)d_in[8];
    const float* v0  = (const float*)d_in[9];
    const float* Wl1 = (const float*)d_in[10];
    const float* Wr1 = (const float*)d_in[11];
    const float* att1= (const float*)d_in[12];
    const float* b1  = (const float*)d_in[13];
    const float* g1  = (const float*)d_in[14];
    const float* be1 = (const float*)d_in[15];
    const float* m1  = (const float*)d_in[16];
    const float* v1  = (const float*)d_in[17];
    const float* Wl2 = (const float*)d_in[18];
    const float* Wr2 = (const float*)d_in[19];
    const float* att2= (const float*)d_in[20];
    const float* b2  = (const float*)d_in[21];
    float* out = (float*)d_out;

    float *p_xlr, *p_h, *p_xl2, *p_xr2;
    int *p_deg, *p_cursor, *p_rowptr, *p_csr, *p_bsum, *p_bflag;
    __nv_bfloat16 *p_xhi, *p_xlo, *p_hhi, *p_hlo;
    __nv_bfloat16 *p_w0h, *p_w0l, *p_w1h, *p_w1l;
    cudaGetSymbolAddress((void**)&p_xlr, g_xlr);
    cudaGetSymbolAddress((void**)&p_h, g_h);
    cudaGetSymbolAddress((void**)&p_xl2, g_xl2);
    cudaGetSymbolAddress((void**)&p_xr2, g_xr2);
    cudaGetSymbolAddress((void**)&p_deg, g_deg);
    cudaGetSymbolAddress((void**)&p_cursor, g_cursor);
    cudaGetSymbolAddress((void**)&p_rowptr, g_rowptr);
    cudaGetSymbolAddress((void**)&p_csr, g_csr);
    cudaGetSymbolAddress((void**)&p_bsum, g_bsum);
    cudaGetSymbolAddress((void**)&p_bflag, g_bflag);
    cudaGetSymbolAddress((void**)&p_xhi, g_xhi);
    cudaGetSymbolAddress((void**)&p_xlo, g_xlo);
    cudaGetSymbolAddress((void**)&p_hhi, g_hhi);
    cudaGetSymbolAddress((void**)&p_hlo, g_hlo);
    cudaGetSymbolAddress((void**)&p_w0h, g_w0h);
    cudaGetSymbolAddress((void**)&p_w0l, g_w0l);
    cudaGetSymbolAddress((void**)&p_w1h, g_w1h);
    cudaGetSymbolAddress((void**)&p_w1l, g_w1l);

    cudaFuncSetAttribute(hmma_dual_gemm<INDIM>,
                         cudaFuncAttributeMaxDynamicSharedMemorySize, GSMEM);
    cudaFuncSetAttribute(hmma_dual_gemm<HCDIM>,
                         cudaFuncAttributeMaxDynamicSharedMemorySize, GSMEM);

    int eBlocks = (ETOT + 255) / 256;
    int nodeWarpBlocks = (NNODES * 32 + 255) / 256;
    int node2WarpBlocks = (NNODES * 64 + 255) / 256;
    dim3 gemmGrid(NOUT / 128, (NNODES + 127) / 128);
    dim3 wtB(32, 8);

    // ===== prep: bf16 splits (+zeroing) + merged wtrans + CSR build =====
    xsplit_kernel<<<(NNODES * INDIM + 255) / 256, 256>>>(x, NNODES * INDIM,
                                                         p_xhi, p_xlo, p_deg,
                                                         p_xl2, p_xr2, p_bflag);
    wtrans_all_kernel<<<dim3(INDIM / 32, 8, 4), wtB>>>(Wl0, Wr0, Wl1, Wr1,
                                                       p_w0h, p_w0l, p_w1h, p_w1l);
    deg_kernel<<<eBlocks, 256>>>(ei, p_deg);
    scan_kernel<<<SCAN_BLOCKS, 1024>>>(p_deg, p_rowptr, p_cursor, p_bsum, p_bflag);
    scatter_kernel<<<eBlocks, 256>>>(ei, p_cursor, p_csr);

    // ===== Layer 0 =====
    hmma_dual_gemm<INDIM><<<gemmGrid, 256, GSMEM>>>(p_xhi, p_xlo, p_w0h, p_w0l,
                                                    p_xlr, NNODES);
    node_gat_kernel<<<node2WarpBlocks, 256>>>(p_rowptr, p_csr, p_xlr, att0,
                                              b0, g0, be0, m0, v0,
                                              p_h, p_hhi, p_hlo,
                                              nullptr, nullptr, nullptr, nullptr, 0);

    // ===== Layer 1 (+ fused layer-2 projection) =====
    hmma_dual_gemm<HCDIM><<<gemmGrid, 256, GSMEM>>>(p_hhi, p_hlo, p_w1h, p_w1l,
                                                    p_xlr, NNODES);
    node_gat_kernel<<<node2WarpBlocks, 256>>>(p_rowptr, p_csr, p_xlr, att1,
                                              b1, g1, be1, m1, v1,
                                              p_h, p_hhi, p_hlo,
                                              Wl2, Wr2, p_xl2, p_xr2, 1);

    // ===== Layer 2 =====
    node_gat2_kernel<<<nodeWarpBlocks, 256>>>(p_rowptr, p_csr, p_xl2, p_xr2,
                                              att2, b2, out);
}